// round 11
// baseline (speedup 1.0000x reference)
#include <cuda_runtime.h>
#include <cuda_fp16.h>
#include <cstdint>

// KANLinear, round 11: GEMM with 64x64 warp tiles (CTA 128x256, 8 warps,
// 3-stage cp.async, 1 CTA/SM) to cut LDS bytes/mma from 187 to 125 and
// leave tensor as sole limiter. af parallelism doubled (AF_CG=32).

#define NROWS 32768
#define FDIM  512
#define UDIM  512
#define NCHUNK 128
#define NKSTEP 256
#define AF_CG  32
#define AF_CPB (NCHUNK / AF_CG)     // 4 chunks per af block

#define BIG    4                    // ksteps per stage
#define NIT    (NKSTEP / BIG)       // 64
#define STG_BYTES 49152             // 16KB A + 32KB B
#define NSTG   3
#define SMEM_TOTAL (NSTG * STG_BYTES)   // 147456

__device__ float  g_xn [(size_t)NROWS * FDIM];            // 64 MB LN output
__device__ __half g_btf[(size_t)64 * NKSTEP * 32 * 4];    // 4 MB B frags
__device__ __half g_af [(size_t)2048 * NKSTEP * 32 * 8];  // 256 MB A frags

#define SIG(L) ((((L) & 3) << 3) | (((L) >> 2) ^ ((((L) & 3) << 1) & 7)))

__device__ __forceinline__ uint32_t smem_u32(const void* p) {
    uint32_t a;
    asm("{ .reg .u64 t; cvta.to.shared.u64 t, %1; cvt.u32.u64 %0, t; }"
        : "=r"(a) : "l"(p));
    return a;
}
#define CP_ASYNC16(dst_u32, src_ptr) \
    asm volatile("cp.async.cg.shared.global [%0], [%1], 16;" \
                 :: "r"(dst_u32), "l"(src_ptr) : "memory")
#define CP_COMMIT() asm volatile("cp.async.commit_group;" ::: "memory")
#define CP_WAIT1()  asm volatile("cp.async.wait_group 1;" ::: "memory")

// ---------------------------------------------------------------------------
// Kernel 1: LayerNorm (unchanged, passing)
// ---------------------------------------------------------------------------
__global__ __launch_bounds__(128) void ln_kernel(const float* __restrict__ x,
                                                 const float* __restrict__ gamma,
                                                 const float* __restrict__ beta) {
    int row = blockIdx.x, tid = threadIdx.x;
    const float4* xr = reinterpret_cast<const float4*>(x + (size_t)row * FDIM);
    float4 v = xr[tid];
    __shared__ float red[4], red2[4];
    float s = v.x + v.y + v.z + v.w;
    #pragma unroll
    for (int o = 16; o > 0; o >>= 1) s += __shfl_xor_sync(~0u, s, o);
    if ((tid & 31) == 0) red[tid >> 5] = s;
    __syncthreads();
    float mean = (red[0] + red[1] + red[2] + red[3]) * (1.0f / FDIM);
    float dx = v.x - mean, dy = v.y - mean, dz = v.z - mean, dw = v.w - mean;
    float s2 = dx * dx + dy * dy + dz * dz + dw * dw;
    #pragma unroll
    for (int o = 16; o > 0; o >>= 1) s2 += __shfl_xor_sync(~0u, s2, o);
    if ((tid & 31) == 0) red2[tid >> 5] = s2;
    __syncthreads();
    float inv = rsqrtf((red2[0] + red2[1] + red2[2] + red2[3]) * (1.0f / FDIM) + 1e-3f);
    float4 g = reinterpret_cast<const float4*>(gamma)[tid];
    float4 b = reinterpret_cast<const float4*>(beta)[tid];
    float4 o4 = { dx * inv * g.x + b.x, dy * inv * g.y + b.y,
                  dz * inv * g.z + b.z, dw * inv * g.w + b.w };
    reinterpret_cast<float4*>(g_xn + (size_t)row * FDIM)[tid] = o4;
}

// ---------------------------------------------------------------------------
// Kernel 2: B fragments (unchanged, passing)
// ---------------------------------------------------------------------------
__global__ __launch_bounds__(256) void btf_kernel(const float* __restrict__ Wb,
                                                  const float* __restrict__ Ws) {
    int bid = blockIdx.x, t = threadIdx.x;
    int f = bid >> 1;
    int n = ((bid & 1) << 8) + t;
    float w[8];
    w[0] = Wb[(size_t)f * UDIM + n];
    #pragma unroll
    for (int m = 1; m <= 6; ++m)
        w[m] = Ws[(size_t)(f * 6 + m - 1) * UDIM + n];
    w[7] = 0.0f;
    __half2* dst = reinterpret_cast<__half2*>(g_btf);
    size_t s = ((size_t)(n >> 3) * 256 + (f >> 1)) * 32 + (n & 7) * 4;
    #pragma unroll
    for (int mp = 0; mp < 4; ++mp)
        dst[(s + mp) * 2 + (f & 1)] = __floats2half2_rn(w[2 * mp], w[2 * mp + 1]);
}

// ---------------------------------------------------------------------------
// closed-form cubic B-spline (unchanged, passing)
// ---------------------------------------------------------------------------
__device__ __forceinline__ void gen8(float xv, float t0, float inv_h, float* v) {
    float xr = (xv - t0) * inv_h;
    float fi = floorf(xr);
    int   i  = (int)fi;
    float s  = xr - fi;
    float s2 = s * s, s3 = s2 * s;
    float u  = 1.0f - s;
    const float c6 = 1.0f / 6.0f;
    float B0 = c6 * u * u * u;
    float B1 = c6 * (3.0f * s3 - 6.0f * s2 + 4.0f);
    float B2 = c6 * (-3.0f * s3 + 3.0f * s2 + 3.0f * s + 1.0f);
    float B3 = c6 * s3;
    bool valid = (xr >= 0.0f) && (i <= 8);
    v[0] = fmaxf(xv, 0.0f);
    #pragma unroll
    for (int j = 0; j < 6; ++j) {
        int d = i - j;
        float bv = (d == 3) ? B0 : (d == 2) ? B1 : (d == 1) ? B2 : (d == 0) ? B3 : 0.0f;
        v[1 + j] = valid ? bv : 0.0f;
    }
    v[7] = 0.0f;
}

// ---------------------------------------------------------------------------
// Kernel 3: A fragments -> gmem. Grid (32 chunk-groups, 256 row-blocks).
// Frag indexing identical to passing rounds 8-10.
// ---------------------------------------------------------------------------
__global__ __launch_bounds__(256) void af_kernel(const float* __restrict__ grid_knots) {
    __shared__ float sx[128][18];                 // 16 feats + pad
    __shared__ __align__(16) char st[2][8192];
    const int tid = threadIdx.x;
    const float t0    = __ldg(grid_knots);
    const float inv_h = 1.0f / (__ldg(grid_knots + 1) - t0);

    const int c0 = blockIdx.x * AF_CPB;
    const int rb = blockIdx.y;

    // stage x: 128 rows x 16 feats, coalesced float4 loads
    for (int idx = tid; idx < 128 * 4; idx += 256) {
        int row = idx >> 2, qc = idx & 3;
        float4 v = __ldg(reinterpret_cast<const float4*>(
            g_xn + (size_t)(rb * 128 + row) * FDIM + c0 * 4) + qc);
        sx[row][qc * 4 + 0] = v.x;
        sx[row][qc * 4 + 1] = v.y;
        sx[row][qc * 4 + 2] = v.z;
        sx[row][qc * 4 + 3] = v.w;
    }
    __syncthreads();

    const int gr = tid >> 1;
    const int gh = tid & 1;
    const int mt = gr >> 4;
    const int g7 = gr & 7;
    const int hi = (gr >> 3) & 1;

    const int mtc = tid >> 5;
    const int ghc = (tid >> 4) & 1;
    const int qo  = (tid & 15) * 2;
    const size_t mtG0 = (size_t)rb * 8;

    #pragma unroll 1
    for (int cc = 0; cc < AF_CPB; ++cc) {
        const int c   = c0 + cc;
        const int buf = cc & 1;
        float xv0 = sx[gr][cc * 4 + gh * 2];
        float xv1 = sx[gr][cc * 4 + gh * 2 + 1];
        float vE[8], vO[8];
        gen8(xv0, t0, inv_h, vE);
        gen8(xv1, t0, inv_h, vO);
        char* ab = st[buf] + (mt * 2 + gh) * 512;
        #pragma unroll
        for (int t = 0; t < 4; ++t) {
            int L = g7 * 4 + t;
            int off = SIG(L) * 16 + hi * 4;
            *reinterpret_cast<__half2*>(ab + off) =
                __floats2half2_rn(vE[2 * t], vE[2 * t + 1]);
            *reinterpret_cast<__half2*>(ab + off + 8) =
                __floats2half2_rn(vO[2 * t], vO[2 * t + 1]);
        }
        __syncthreads();
        {
            const uint4* src = reinterpret_cast<const uint4*>(
                st[buf] + (mtc * 2 + ghc) * 512) + qo;
            uint4* dst = reinterpret_cast<uint4*>(g_af) +
                ((mtG0 + mtc) * NKSTEP + (c * 2 + ghc)) * 32 + qo;
            dst[0] = src[0];
            dst[1] = src[1];
        }
    }
}

// ---------------------------------------------------------------------------
// Kernel 4: cp.async 3-stage pipelined HMMA GEMM, warp tile 64x64.
// 256 thr = 8 warps (2m x 4n), CTA tile 128x256, stage = 4 ksteps.
// Stage smem: A [mt 8][ks 4][slot 32]u4 (16KB), B [nt 32][ks 4][16]u4 (32KB).
// ---------------------------------------------------------------------------
__global__ __launch_bounds__(256, 1) void kan_mma_kernel(
    const float* __restrict__ bias, float* __restrict__ out)
{
    extern __shared__ __align__(16) char smem[];
    const uint32_t sbase = smem_u32(smem);

    const int tid  = threadIdx.x;
    const int lane = tid & 31;
    const int wid  = tid >> 5;
    const int wm   = wid >> 2;              // 0..1
    const int wn   = wid & 3;               // 0..3
    const int row0 = blockIdx.y * 128;
    const int col0 = blockIdx.x * 256;

    const uint4* agm = reinterpret_cast<const uint4*>(g_af);
    const uint4* bgm = reinterpret_cast<const uint4*>(g_btf);
    const size_t arow0 = (size_t)blockIdx.y * 8;   // 8 mt rows
    const size_t brow0 = (size_t)blockIdx.x * 32;  // 32 nt rows

    auto issue_stage = [&](int stg, int ks0) {
        const uint32_t da = sbase + stg * STG_BYTES;
        const uint32_t db = da + 16384;
        #pragma unroll
        for (int r = 0; r < 4; ++r) {       // A: 1024 uint4
            int q = tid + r * 256;
            const uint4* srcA = agm +
                ((arow0 + (q >> 7)) * NKSTEP + ks0 + ((q >> 5) & 3)) * 32 + (q & 31);
            CP_ASYNC16(da + q * 16, srcA);
        }
        #pragma unroll
        for (int r = 0; r < 8; ++r) {       // B: 2048 uint4
            int q = tid + r * 256;
            const uint4* srcB = bgm +
                ((brow0 + (q >> 6)) * NKSTEP + ks0 + ((q >> 4) & 3)) * 16 + (q & 15);
            CP_ASYNC16(db + q * 16, srcB);
        }
        CP_COMMIT();
    };

    // acc init = bias  (warp n-tile is 64 wide: wn*64 + in*8)
    float acc[4][8][4];
    #pragma unroll
    for (int in = 0; in < 8; ++in) {
        float2 bb = *reinterpret_cast<const float2*>(
            bias + col0 + wn * 64 + in * 8 + (lane & 3) * 2);
        #pragma unroll
        for (int im = 0; im < 4; ++im) {
            acc[im][in][0] = bb.x; acc[im][in][1] = bb.y;
            acc[im][in][2] = bb.x; acc[im][in][3] = bb.y;
        }
    }

    issue_stage(0, 0);
    issue_stage(1, BIG);

    const int aslot = SIG(lane);
    int stg = 0;
    for (int it = 0; it < NIT; ++it) {
        CP_WAIT1();
        __syncthreads();
        if (it + 2 < NIT) issue_stage((stg + 2) % NSTG, (it + 2) * BIG);

        const char* sa = smem + stg * STG_BYTES;
        const char* sb = sa + 16384;
        #pragma unroll
        for (int ks = 0; ks < BIG; ++ks) {
            uint4 a[4];
            #pragma unroll
            for (int im = 0; im < 4; ++im)
                a[im] = *reinterpret_cast<const uint4*>(
                    sa + (((wm * 4 + im) * 4 + ks) * 32 + aslot) * 16);
            uint2 b[8];
            #pragma unroll
            for (int in = 0; in < 8; ++in)
                b[in] = *reinterpret_cast<const uint2*>(
                    sb + (((wn * 8 + in) * 4 + ks) * 32 + lane) * 8);
            #pragma unroll
            for (int im = 0; im < 4; ++im)
                #pragma unroll
                for (int in = 0; in < 8; ++in) {
                    asm volatile(
                        "mma.sync.aligned.m16n8k16.row.col.f32.f16.f16.f32 "
                        "{%0,%1,%2,%3}, {%4,%5,%6,%7}, {%8,%9}, {%0,%1,%2,%3};"
                        : "+f"(acc[im][in][0]), "+f"(acc[im][in][1]),
                          "+f"(acc[im][in][2]), "+f"(acc[im][in][3])
                        : "r"(a[im].x), "r"(a[im].y), "r"(a[im].z), "r"(a[im].w),
                          "r"(b[in].x), "r"(b[in].y));
                }
        }
        stg = (stg + 1) % NSTG;
    }

    // epilogue
    const int g  = lane >> 2;
    const int tq = lane & 3;
    #pragma unroll
    for (int im = 0; im < 4; ++im) {
        int row = row0 + wm * 64 + im * 16 + g;
        #pragma unroll
        for (int in = 0; in < 8; ++in) {
            int col = col0 + wn * 64 + in * 8 + tq * 2;
            *reinterpret_cast<float2*>(out + (size_t)row * UDIM + col)
                = make_float2(acc[im][in][0], acc[im][in][1]);
            *reinterpret_cast<float2*>(out + (size_t)(row + 8) * UDIM + col)
                = make_float2(acc[im][in][2], acc[im][in][3]);
        }
    }
}

// ---------------------------------------------------------------------------
extern "C" void kernel_launch(void* const* d_in, const int* in_sizes, int n_in,
                              void* d_out, int out_size) {
    const float* x     = (const float*)d_in[0];
    const float* gamma = (const float*)d_in[1];
    const float* beta  = (const float*)d_in[2];
    const float* Wb    = (const float*)d_in[3];
    const float* bias  = (const float*)d_in[4];
    const float* Ws    = (const float*)d_in[5];
    const float* grid  = (const float*)d_in[6];
    float* out = (float*)d_out;

    cudaFuncSetAttribute(kan_mma_kernel,
                         cudaFuncAttributeMaxDynamicSharedMemorySize, SMEM_TOTAL);

    ln_kernel<<<NROWS, 128>>>(x, gamma, beta);
    btf_kernel<<<1024, 256>>>(Wb, Ws);
    af_kernel<<<dim3(AF_CG, NROWS / 128), 256>>>(grid);
    kan_mma_kernel<<<dim3(UDIM / 256, NROWS / 128), 256, SMEM_TOTAL>>>(bias, out);
}

// round 12
// speedup vs baseline: 1.1371x; 1.1371x over previous
#include <cuda_runtime.h>
#include <cuda_fp16.h>
#include <cstdint>

// KANLinear, round 12: GEMM reverted to the round-10 optimum (313us).
// New fused LN + A-fragment kernel (afln): one block per 16-row group,
// LN in smem, then warp-autonomous frag generation via register shuffles
// and coalesced STG.128 — no g_xn round-trip, no per-chunk barriers.

#define NROWS 32768
#define FDIM  512
#define UDIM  512
#define NKSTEP 256

#define BIG    4
#define NIT    (NKSTEP / BIG)       // 64
#define STG_BYTES 32768             // 16KB A + 16KB B
#define NSTG   3
#define SMEM_TOTAL (NSTG * STG_BYTES)

__device__ __half g_btf[(size_t)64 * NKSTEP * 32 * 4];    // 4 MB B frags
__device__ __half g_af [(size_t)2048 * NKSTEP * 32 * 8];  // 256 MB A frags

#define SIG(L) ((((L) & 3) << 3) | (((L) >> 2) ^ ((((L) & 3) << 1) & 7)))

__device__ __forceinline__ uint32_t smem_u32(const void* p) {
    uint32_t a;
    asm("{ .reg .u64 t; cvta.to.shared.u64 t, %1; cvt.u32.u64 %0, t; }"
        : "=r"(a) : "l"(p));
    return a;
}
#define CP_ASYNC16(dst_u32, src_ptr) \
    asm volatile("cp.async.cg.shared.global [%0], [%1], 16;" \
                 :: "r"(dst_u32), "l"(src_ptr) : "memory")
#define CP_COMMIT() asm volatile("cp.async.commit_group;" ::: "memory")
#define CP_WAIT1()  asm volatile("cp.async.wait_group 1;" ::: "memory")

// ---------------------------------------------------------------------------
// Kernel 1: B fragments (unchanged, passing)
// ---------------------------------------------------------------------------
__global__ __launch_bounds__(256) void btf_kernel(const float* __restrict__ Wb,
                                                  const float* __restrict__ Ws) {
    int bid = blockIdx.x, t = threadIdx.x;
    int f = bid >> 1;
    int n = ((bid & 1) << 8) + t;
    float w[8];
    w[0] = Wb[(size_t)f * UDIM + n];
    #pragma unroll
    for (int m = 1; m <= 6; ++m)
        w[m] = Ws[(size_t)(f * 6 + m - 1) * UDIM + n];
    w[7] = 0.0f;
    __half2* dst = reinterpret_cast<__half2*>(g_btf);
    size_t s = ((size_t)(n >> 3) * 256 + (f >> 1)) * 32 + (n & 7) * 4;
    #pragma unroll
    for (int mp = 0; mp < 4; ++mp)
        dst[(s + mp) * 2 + (f & 1)] = __floats2half2_rn(w[2 * mp], w[2 * mp + 1]);
}

// ---------------------------------------------------------------------------
// closed-form cubic B-spline (unchanged, passing)
// ---------------------------------------------------------------------------
__device__ __forceinline__ void gen8(float xv, float t0, float inv_h, float* v) {
    float xr = (xv - t0) * inv_h;
    float fi = floorf(xr);
    int   i  = (int)fi;
    float s  = xr - fi;
    float s2 = s * s, s3 = s2 * s;
    float u  = 1.0f - s;
    const float c6 = 1.0f / 6.0f;
    float B0 = c6 * u * u * u;
    float B1 = c6 * (3.0f * s3 - 6.0f * s2 + 4.0f);
    float B2 = c6 * (-3.0f * s3 + 3.0f * s2 + 3.0f * s + 1.0f);
    float B3 = c6 * s3;
    bool valid = (xr >= 0.0f) && (i <= 8);
    v[0] = fmaxf(xv, 0.0f);
    #pragma unroll
    for (int j = 0; j < 6; ++j) {
        int d = i - j;
        float bv = (d == 3) ? B0 : (d == 2) ? B1 : (d == 1) ? B2 : (d == 0) ? B3 : 0.0f;
        v[1 + j] = valid ? bv : 0.0f;
    }
    v[7] = 0.0f;
}

// ---------------------------------------------------------------------------
// Kernel 2: fused LN + A fragments.
// Block = 256 thr = 8 warps; one block per 16-row group (mtG = blockIdx.x).
// 1) stage raw x[16][512] in smem (stride 514 -> conflict-free col reads)
// 2) LN: 2 rows per warp (shfl reductions), normalize in place
// 3) frag gen: warp w handles ksteps {w, w+8, ...}. Lane = 16*featsel +
//    row_local computes gen8, packs 4 half2; 4x4 shuffle-transpose gathers
//    the 16B block for logical slot L=lane; STG.128 at SIG(L) -> coalesced.
// Output byte-layout identical to rounds 8-11.
// ---------------------------------------------------------------------------
__global__ __launch_bounds__(256) void afln_kernel(
    const float* __restrict__ x,
    const float* __restrict__ gamma,
    const float* __restrict__ beta,
    const float* __restrict__ grid_knots)
{
    __shared__ float sx[16][514];
    __shared__ float sg[512], sb[512];
    __shared__ float smean[16], sinv[16];

    const int tid  = threadIdx.x;
    const int lane = tid & 31;
    const int wq   = tid >> 5;
    const int R0   = blockIdx.x * 16;

    const float t0    = __ldg(grid_knots);
    const float inv_h = 1.0f / (__ldg(grid_knots + 1) - t0);

    // ---- stage x (coalesced float4) + gamma/beta ----
    for (int idx = tid; idx < 16 * 128; idx += 256) {
        int row = idx >> 7, q = idx & 127;
        float4 v = __ldg(reinterpret_cast<const float4*>(
            x + (size_t)(R0 + row) * FDIM) + q);
        *reinterpret_cast<float2*>(&sx[row][q * 4])     = make_float2(v.x, v.y);
        *reinterpret_cast<float2*>(&sx[row][q * 4 + 2]) = make_float2(v.z, v.w);
    }
    for (int idx = tid; idx < 512; idx += 256) {
        sg[idx] = __ldg(gamma + idx);
        sb[idx] = __ldg(beta + idx);
    }
    __syncthreads();

    // ---- LN stats: warp wq handles rows 2wq, 2wq+1 ----
    #pragma unroll
    for (int rr = 0; rr < 2; ++rr) {
        int r = wq * 2 + rr;
        float s = 0.0f;
        #pragma unroll
        for (int i = 0; i < 16; ++i) s += sx[r][lane + 32 * i];
        #pragma unroll
        for (int o = 16; o > 0; o >>= 1) s += __shfl_xor_sync(~0u, s, o);
        float mean = s * (1.0f / FDIM);
        float s2 = 0.0f;
        #pragma unroll
        for (int i = 0; i < 16; ++i) {
            float d = sx[r][lane + 32 * i] - mean;
            s2 += d * d;
        }
        #pragma unroll
        for (int o = 16; o > 0; o >>= 1) s2 += __shfl_xor_sync(~0u, s2, o);
        if (lane == 0) {
            smean[r] = mean;
            sinv[r]  = rsqrtf(s2 * (1.0f / FDIM) + 1e-3f);
        }
    }
    __syncthreads();

    // ---- normalize in place ----
    for (int idx = tid; idx < 16 * 512; idx += 256) {
        int row = idx >> 9, col = idx & 511;
        float v = (sx[row][col] - smean[row]) * sinv[row] * sg[col] + sb[col];
        sx[row][col] = v;
    }
    __syncthreads();

    // ---- frag generation: no more barriers ----
    const int rl = lane & 15;          // source row_local
    const int fs = lane >> 4;          // source feature select (0/1)
    const int g7 = lane >> 2;          // target group
    const int t  = lane & 3;           // target k-pair
    uint4* dst0 = reinterpret_cast<uint4*>(g_af) +
                  (size_t)blockIdx.x * NKSTEP * 32 + SIG(lane);

    #pragma unroll 1
    for (int j = 0; j < NKSTEP / 8; ++j) {
        const int ks = wq + j * 8;
        float xv = sx[rl][2 * ks + fs];
        float v[8];
        gen8(xv, t0, inv_h, v);
        uint32_t h2[4];
        #pragma unroll
        for (int tt = 0; tt < 4; ++tt) {
            __half2 hh = __floats2half2_rn(v[2 * tt], v[2 * tt + 1]);
            h2[tt] = *reinterpret_cast<uint32_t*>(&hh);
        }
        // 4x4 shuffle transpose: gather h2[t] from the 4 source lanes
        uint32_t w0 = 0, w1 = 0, w2 = 0, w3 = 0;
        #pragma unroll
        for (int tt = 0; tt < 4; ++tt) {
            uint32_t a0 = __shfl_sync(~0u, h2[tt], g7);        // row g7,   f0
            uint32_t a1 = __shfl_sync(~0u, h2[tt], g7 + 8);    // row g7+8, f0
            uint32_t a2 = __shfl_sync(~0u, h2[tt], g7 + 16);   // row g7,   f1
            uint32_t a3 = __shfl_sync(~0u, h2[tt], g7 + 24);   // row g7+8, f1
            if (t == tt) { w0 = a0; w1 = a1; w2 = a2; w3 = a3; }
        }
        uint4 o = make_uint4(w0, w1, w2, w3);
        dst0[(size_t)ks * 32] = o;
    }
}

// ---------------------------------------------------------------------------
// Kernel 3: cp.async 3-stage pipelined HMMA GEMM (round-10 verbatim, 313us).
// ---------------------------------------------------------------------------
__global__ __launch_bounds__(256, 2) void kan_mma_kernel(
    const float* __restrict__ bias, float* __restrict__ out)
{
    extern __shared__ __align__(16) char smem[];
    const uint32_t sbase = smem_u32(smem);

    const int tid  = threadIdx.x;
    const int lane = tid & 31;
    const int wid  = tid >> 5;
    const int wm   = wid >> 2;
    const int wn   = wid & 3;
    const int row0 = blockIdx.y * 128;
    const int col0 = blockIdx.x * 128;

    const uint4* agm = reinterpret_cast<const uint4*>(g_af);
    const uint4* bgm = reinterpret_cast<const uint4*>(g_btf);
    const size_t arow0 = (size_t)blockIdx.y * 8;
    const size_t brow0 = (size_t)blockIdx.x * 16;

    auto issue_stage = [&](int stg, int ks0) {
        const uint32_t da = sbase + stg * STG_BYTES;
        const uint32_t db = da + 16384;
        #pragma unroll
        for (int r = 0; r < 4; ++r) {
            int q = tid + r * 256;
            const uint4* srcA = agm +
                ((arow0 + (q >> 7)) * NKSTEP + ks0 + ((q >> 5) & 3)) * 32 + (q & 31);
            CP_ASYNC16(da + q * 16, srcA);
        }
        #pragma unroll
        for (int r = 0; r < 4; ++r) {
            int q = tid + r * 256;
            const uint4* srcB = bgm +
                ((brow0 + (q >> 6)) * NKSTEP + ks0 + ((q >> 4) & 3)) * 16 + (q & 15);
            CP_ASYNC16(db + q * 16, srcB);
        }
        CP_COMMIT();
    };

    float acc[4][4][4];
    #pragma unroll
    for (int in = 0; in < 4; ++in) {
        float2 bb = *reinterpret_cast<const float2*>(
            bias + col0 + wn * 32 + in * 8 + (lane & 3) * 2);
        #pragma unroll
        for (int im = 0; im < 4; ++im) {
            acc[im][in][0] = bb.x; acc[im][in][1] = bb.y;
            acc[im][in][2] = bb.x; acc[im][in][3] = bb.y;
        }
    }

    issue_stage(0, 0);
    issue_stage(1, BIG);

    const int aslot = SIG(lane);
    int stg = 0;
    for (int it = 0; it < NIT; ++it) {
        CP_WAIT1();
        __syncthreads();
        if (it + 2 < NIT) issue_stage((stg + 2) % NSTG, (it + 2) * BIG);

        const char* sa = smem + stg * STG_BYTES;
        const char* sb = sa + 16384;
        #pragma unroll
        for (int ks = 0; ks < BIG; ++ks) {
            uint4 a[4];
            #pragma unroll
            for (int im = 0; im < 4; ++im)
                a[im] = *reinterpret_cast<const uint4*>(
                    sa + (((wm * 4 + im) * 4 + ks) * 32 + aslot) * 16);
            uint2 b[4];
            #pragma unroll
            for (int in = 0; in < 4; ++in)
                b[in] = *reinterpret_cast<const uint2*>(
                    sb + (((wn * 4 + in) * 4 + ks) * 32 + lane) * 8);
            #pragma unroll
            for (int im = 0; im < 4; ++im)
                #pragma unroll
                for (int in = 0; in < 4; ++in) {
                    asm volatile(
                        "mma.sync.aligned.m16n8k16.row.col.f32.f16.f16.f32 "
                        "{%0,%1,%2,%3}, {%4,%5,%6,%7}, {%8,%9}, {%0,%1,%2,%3};"
                        : "+f"(acc[im][in][0]), "+f"(acc[im][in][1]),
                          "+f"(acc[im][in][2]), "+f"(acc[im][in][3])
                        : "r"(a[im].x), "r"(a[im].y), "r"(a[im].z), "r"(a[im].w),
                          "r"(b[in].x), "r"(b[in].y));
                }
        }
        stg = (stg + 1) % NSTG;
    }

    const int g  = lane >> 2;
    const int tq = lane & 3;
    #pragma unroll
    for (int im = 0; im < 4; ++im) {
        int row = row0 + wm * 64 + im * 16 + g;
        #pragma unroll
        for (int in = 0; in < 4; ++in) {
            int col = col0 + wn * 32 + in * 8 + tq * 2;
            *reinterpret_cast<float2*>(out + (size_t)row * UDIM + col)
                = make_float2(acc[im][in][0], acc[im][in][1]);
            *reinterpret_cast<float2*>(out + (size_t)(row + 8) * UDIM + col)
                = make_float2(acc[im][in][2], acc[im][in][3]);
        }
    }
}

// ---------------------------------------------------------------------------
extern "C" void kernel_launch(void* const* d_in, const int* in_sizes, int n_in,
                              void* d_out, int out_size) {
    const float* x     = (const float*)d_in[0];
    const float* gamma = (const float*)d_in[1];
    const float* beta  = (const float*)d_in[2];
    const float* Wb    = (const float*)d_in[3];
    const float* bias  = (const float*)d_in[4];
    const float* Ws    = (const float*)d_in[5];
    const float* grid  = (const float*)d_in[6];
    float* out = (float*)d_out;

    cudaFuncSetAttribute(kan_mma_kernel,
                         cudaFuncAttributeMaxDynamicSharedMemorySize, SMEM_TOTAL);

    btf_kernel<<<1024, 256>>>(Wb, Ws);
    afln_kernel<<<NROWS / 16, 256>>>(x, gamma, beta, grid);
    kan_mma_kernel<<<dim3(UDIM / 128, NROWS / 128), 256, SMEM_TOTAL>>>(bias, out);
}

// round 13
// speedup vs baseline: 1.1628x; 1.0226x over previous
#include <cuda_runtime.h>
#include <cuda_fp16.h>
#include <cstdint>

// KANLinear, round 13: afln frag-gen reworked — warp-private smem transpose
// (4 STS.32 + 1 LDS.128 + 1 STG.128 per kstep, __syncwarp only) replaces the
// 16-shuffle transpose; LN affine folded into the gen loop. GEMM and btf
// frozen (round-10/12 passing versions). g_af bytes identical by design.

#define NROWS 32768
#define FDIM  512
#define UDIM  512
#define NKSTEP 256

#define BIG    4
#define NIT    (NKSTEP / BIG)       // 64
#define STG_BYTES 32768             // 16KB A + 16KB B
#define NSTG   3
#define SMEM_TOTAL (NSTG * STG_BYTES)

__device__ __half g_btf[(size_t)64 * NKSTEP * 32 * 4];    // 4 MB B frags
__device__ __half g_af [(size_t)2048 * NKSTEP * 32 * 8];  // 256 MB A frags

#define SIG(L) ((((L) & 3) << 3) | (((L) >> 2) ^ ((((L) & 3) << 1) & 7)))

__device__ __forceinline__ uint32_t smem_u32(const void* p) {
    uint32_t a;
    asm("{ .reg .u64 t; cvta.to.shared.u64 t, %1; cvt.u32.u64 %0, t; }"
        : "=r"(a) : "l"(p));
    return a;
}
#define CP_ASYNC16(dst_u32, src_ptr) \
    asm volatile("cp.async.cg.shared.global [%0], [%1], 16;" \
                 :: "r"(dst_u32), "l"(src_ptr) : "memory")
#define CP_COMMIT() asm volatile("cp.async.commit_group;" ::: "memory")
#define CP_WAIT1()  asm volatile("cp.async.wait_group 1;" ::: "memory")

// ---------------------------------------------------------------------------
// Kernel 1: B fragments (unchanged, passing)
// ---------------------------------------------------------------------------
__global__ __launch_bounds__(256) void btf_kernel(const float* __restrict__ Wb,
                                                  const float* __restrict__ Ws) {
    int bid = blockIdx.x, t = threadIdx.x;
    int f = bid >> 1;
    int n = ((bid & 1) << 8) + t;
    float w[8];
    w[0] = Wb[(size_t)f * UDIM + n];
    #pragma unroll
    for (int m = 1; m <= 6; ++m)
        w[m] = Ws[(size_t)(f * 6 + m - 1) * UDIM + n];
    w[7] = 0.0f;
    __half2* dst = reinterpret_cast<__half2*>(g_btf);
    size_t s = ((size_t)(n >> 3) * 256 + (f >> 1)) * 32 + (n & 7) * 4;
    #pragma unroll
    for (int mp = 0; mp < 4; ++mp)
        dst[(s + mp) * 2 + (f & 1)] = __floats2half2_rn(w[2 * mp], w[2 * mp + 1]);
}

// ---------------------------------------------------------------------------
// closed-form cubic B-spline (unchanged, passing)
// ---------------------------------------------------------------------------
__device__ __forceinline__ void gen8(float xv, float t0, float inv_h, float* v) {
    float xr = (xv - t0) * inv_h;
    float fi = floorf(xr);
    int   i  = (int)fi;
    float s  = xr - fi;
    float s2 = s * s, s3 = s2 * s;
    float u  = 1.0f - s;
    const float c6 = 1.0f / 6.0f;
    float B0 = c6 * u * u * u;
    float B1 = c6 * (3.0f * s3 - 6.0f * s2 + 4.0f);
    float B2 = c6 * (-3.0f * s3 + 3.0f * s2 + 3.0f * s + 1.0f);
    float B3 = c6 * s3;
    bool valid = (xr >= 0.0f) && (i <= 8);
    v[0] = fmaxf(xv, 0.0f);
    #pragma unroll
    for (int j = 0; j < 6; ++j) {
        int d = i - j;
        float bv = (d == 3) ? B0 : (d == 2) ? B1 : (d == 1) ? B2 : (d == 0) ? B3 : 0.0f;
        v[1 + j] = valid ? bv : 0.0f;
    }
    v[7] = 0.0f;
}

// ---------------------------------------------------------------------------
// Kernel 2: fused LN + A fragments, warp-private transpose.
// Block = 256 thr = 8 warps; one block per 16-row group (blockIdx.x).
// Phase 1: stage raw x[16][514] + gamma/beta; LN stats (2 rows/warp).
// Phase 2 (barrier-free): warp wq owns ksteps {wq, wq+8, ...}. Lane
// (fs=lane>>4, rl=lane&15) computes LN-affine inline, gen8, writes 4 half2
// into the warp's 512B scratch at the SIG-swizzled offsets (conflict-free),
// __syncwarp, then LDS.128 at lane*16 and coalesced STG.128.
// ---------------------------------------------------------------------------
__global__ __launch_bounds__(256) void afln_kernel(
    const float* __restrict__ x,
    const float* __restrict__ gamma,
    const float* __restrict__ beta,
    const float* __restrict__ grid_knots)
{
    __shared__ float sx[16][514];
    __shared__ float sg[512], sb[512];
    __shared__ float smean[16], sinv[16];
    __shared__ __align__(16) char swp[8][2][512];

    const int tid  = threadIdx.x;
    const int lane = tid & 31;
    const int wq   = tid >> 5;
    const int R0   = blockIdx.x * 16;

    const float t0    = __ldg(grid_knots);
    const float inv_h = 1.0f / (__ldg(grid_knots + 1) - t0);

    // ---- stage raw x (coalesced float4) + gamma/beta ----
    for (int idx = tid; idx < 16 * 128; idx += 256) {
        int row = idx >> 7, q = idx & 127;
        float4 v = __ldg(reinterpret_cast<const float4*>(
            x + (size_t)(R0 + row) * FDIM) + q);
        *reinterpret_cast<float2*>(&sx[row][q * 4])     = make_float2(v.x, v.y);
        *reinterpret_cast<float2*>(&sx[row][q * 4 + 2]) = make_float2(v.z, v.w);
    }
    for (int idx = tid; idx < 512; idx += 256) {
        sg[idx] = __ldg(gamma + idx);
        sb[idx] = __ldg(beta + idx);
    }
    __syncthreads();

    // ---- LN stats: warp wq handles rows 2wq, 2wq+1 ----
    #pragma unroll
    for (int rr = 0; rr < 2; ++rr) {
        int r = wq * 2 + rr;
        float s = 0.0f;
        #pragma unroll
        for (int i = 0; i < 16; ++i) s += sx[r][lane + 32 * i];
        #pragma unroll
        for (int o = 16; o > 0; o >>= 1) s += __shfl_xor_sync(~0u, s, o);
        float mean = s * (1.0f / FDIM);
        float s2 = 0.0f;
        #pragma unroll
        for (int i = 0; i < 16; ++i) {
            float d = sx[r][lane + 32 * i] - mean;
            s2 += d * d;
        }
        #pragma unroll
        for (int o = 16; o > 0; o >>= 1) s2 += __shfl_xor_sync(~0u, s2, o);
        if (lane == 0) {
            smean[r] = mean;
            sinv[r]  = rsqrtf(s2 * (1.0f / FDIM) + 1e-3f);
        }
    }
    __syncthreads();

    // ---- frag generation (no block barriers) ----
    const int rl = lane & 15;          // row_local
    const int fs = lane >> 4;          // feature select (0/1)
    const int g7 = rl & 7;
    const int hi = (rl >> 3) & 1;
    const float mean = smean[rl];
    const float inv  = sinv[rl];

    // STS offsets within the 512B block (same swizzle bytes as all passing rounds)
    int sts[4];
    #pragma unroll
    for (int t = 0; t < 4; ++t)
        sts[t] = SIG(g7 * 4 + t) * 16 + hi * 4 + fs * 8;

    uint4* dstB = reinterpret_cast<uint4*>(g_af) +
                  (size_t)blockIdx.x * NKSTEP * 32 + lane;

    #pragma unroll 1
    for (int j = 0; j < NKSTEP / 8; ++j) {
        const int ks  = wq + j * 8;
        const int col = 2 * ks + fs;
        float xv = (sx[rl][col] - mean) * inv * sg[col] + sb[col];
        float v[8];
        gen8(xv, t0, inv_h, v);
        char* scr = swp[wq][j & 1];
        #pragma unroll
        for (int t = 0; t < 4; ++t)
            *reinterpret_cast<__half2*>(scr + sts[t]) =
                __floats2half2_rn(v[2 * t], v[2 * t + 1]);
        __syncwarp();
        uint4 o = *reinterpret_cast<const uint4*>(scr + lane * 16);
        dstB[(size_t)ks * 32] = o;
    }
}

// ---------------------------------------------------------------------------
// Kernel 3: cp.async 3-stage pipelined HMMA GEMM (round-10 verbatim, 313us).
// ---------------------------------------------------------------------------
__global__ __launch_bounds__(256, 2) void kan_mma_kernel(
    const float* __restrict__ bias, float* __restrict__ out)
{
    extern __shared__ __align__(16) char smem[];
    const uint32_t sbase = smem_u32(smem);

    const int tid  = threadIdx.x;
    const int lane = tid & 31;
    const int wid  = tid >> 5;
    const int wm   = wid >> 2;
    const int wn   = wid & 3;
    const int row0 = blockIdx.y * 128;
    const int col0 = blockIdx.x * 128;

    const uint4* agm = reinterpret_cast<const uint4*>(g_af);
    const uint4* bgm = reinterpret_cast<const uint4*>(g_btf);
    const size_t arow0 = (size_t)blockIdx.y * 8;
    const size_t brow0 = (size_t)blockIdx.x * 16;

    auto issue_stage = [&](int stg, int ks0) {
        const uint32_t da = sbase + stg * STG_BYTES;
        const uint32_t db = da + 16384;
        #pragma unroll
        for (int r = 0; r < 4; ++r) {
            int q = tid + r * 256;
            const uint4* srcA = agm +
                ((arow0 + (q >> 7)) * NKSTEP + ks0 + ((q >> 5) & 3)) * 32 + (q & 31);
            CP_ASYNC16(da + q * 16, srcA);
        }
        #pragma unroll
        for (int r = 0; r < 4; ++r) {
            int q = tid + r * 256;
            const uint4* srcB = bgm +
                ((brow0 + (q >> 6)) * NKSTEP + ks0 + ((q >> 4) & 3)) * 16 + (q & 15);
            CP_ASYNC16(db + q * 16, srcB);
        }
        CP_COMMIT();
    };

    float acc[4][4][4];
    #pragma unroll
    for (int in = 0; in < 4; ++in) {
        float2 bb = *reinterpret_cast<const float2*>(
            bias + col0 + wn * 32 + in * 8 + (lane & 3) * 2);
        #pragma unroll
        for (int im = 0; im < 4; ++im) {
            acc[im][in][0] = bb.x; acc[im][in][1] = bb.y;
            acc[im][in][2] = bb.x; acc[im][in][3] = bb.y;
        }
    }

    issue_stage(0, 0);
    issue_stage(1, BIG);

    const int aslot = SIG(lane);
    int stg = 0;
    for (int it = 0; it < NIT; ++it) {
        CP_WAIT1();
        __syncthreads();
        if (it + 2 < NIT) issue_stage((stg + 2) % NSTG, (it + 2) * BIG);

        const char* sa = smem + stg * STG_BYTES;
        const char* sb = sa + 16384;
        #pragma unroll
        for (int ks = 0; ks < BIG; ++ks) {
            uint4 a[4];
            #pragma unroll
            for (int im = 0; im < 4; ++im)
                a[im] = *reinterpret_cast<const uint4*>(
                    sa + (((wm * 4 + im) * 4 + ks) * 32 + aslot) * 16);
            uint2 b[4];
            #pragma unroll
            for (int in = 0; in < 4; ++in)
                b[in] = *reinterpret_cast<const uint2*>(
                    sb + (((wn * 4 + in) * 4 + ks) * 32 + lane) * 8);
            #pragma unroll
            for (int im = 0; im < 4; ++im)
                #pragma unroll
                for (int in = 0; in < 4; ++in) {
                    asm volatile(
                        "mma.sync.aligned.m16n8k16.row.col.f32.f16.f16.f32 "
                        "{%0,%1,%2,%3}, {%4,%5,%6,%7}, {%8,%9}, {%0,%1,%2,%3};"
                        : "+f"(acc[im][in][0]), "+f"(acc[im][in][1]),
                          "+f"(acc[im][in][2]), "+f"(acc[im][in][3])
                        : "r"(a[im].x), "r"(a[im].y), "r"(a[im].z), "r"(a[im].w),
                          "r"(b[in].x), "r"(b[in].y));
                }
        }
        stg = (stg + 1) % NSTG;
    }

    const int g  = lane >> 2;
    const int tq = lane & 3;
    #pragma unroll
    for (int im = 0; im < 4; ++im) {
        int row = row0 + wm * 64 + im * 16 + g;
        #pragma unroll
        for (int in = 0; in < 4; ++in) {
            int col = col0 + wn * 32 + in * 8 + tq * 2;
            *reinterpret_cast<float2*>(out + (size_t)row * UDIM + col)
                = make_float2(acc[im][in][0], acc[im][in][1]);
            *reinterpret_cast<float2*>(out + (size_t)(row + 8) * UDIM + col)
                = make_float2(acc[im][in][2], acc[im][in][3]);
        }
    }
}

// ---------------------------------------------------------------------------
extern "C" void kernel_launch(void* const* d_in, const int* in_sizes, int n_in,
                              void* d_out, int out_size) {
    const float* x     = (const float*)d_in[0];
    const float* gamma = (const float*)d_in[1];
    const float* beta  = (const float*)d_in[2];
    const float* Wb    = (const float*)d_in[3];
    const float* bias  = (const float*)d_in[4];
    const float* Ws    = (const float*)d_in[5];
    const float* grid  = (const float*)d_in[6];
    float* out = (float*)d_out;

    cudaFuncSetAttribute(kan_mma_kernel,
                         cudaFuncAttributeMaxDynamicSharedMemorySize, SMEM_TOTAL);

    btf_kernel<<<1024, 256>>>(Wb, Ws);
    afln_kernel<<<NROWS / 16, 256>>>(x, gamma, beta, grid);
    kan_mma_kernel<<<dim3(UDIM / 128, NROWS / 128), 256, SMEM_TOTAL>>>(bias, out);
}